// round 1
// baseline (speedup 1.0000x reference)
#include <cuda_runtime.h>

#define NROWS 16384
#define DIM   512
#define KNN   10

// Scratch (allocation-free rule: device globals)
__device__ float g_xw[NROWS * DIM];   // 32 MB: x @ A
__device__ float g_sq[NROWS];         // row squared norms
__device__ int   g_idx[NROWS * KNN];  // top-10 neighbor indices per row

// ---------------- row squared norms: one warp per row ----------------
__global__ void sq_kernel(const float* __restrict__ x) {
    int warp = (blockIdx.x * blockDim.x + threadIdx.x) >> 5;
    int lane = threadIdx.x & 31;
    if (warp >= NROWS) return;
    const float4* xr = reinterpret_cast<const float4*>(x + (size_t)warp * DIM);
    float s = 0.f;
#pragma unroll
    for (int i = 0; i < 4; ++i) {
        float4 v = xr[lane + 32 * i];
        s += v.x * v.x + v.y * v.y + v.z * v.z + v.w * v.w;
    }
#pragma unroll
    for (int o = 16; o > 0; o >>= 1) s += __shfl_xor_sync(0xffffffffu, s, o);
    if (lane == 0) g_sq[warp] = s;
}

// ---------------- xW = x @ A : 128x128 tiles, 8x8 micro ----------------
__global__ __launch_bounds__(256, 1) void xw_kernel(const float* __restrict__ x,
                                                    const float* __restrict__ A) {
    __shared__ float As[8][132];
    __shared__ float Bs[8][132];
    const int bm = blockIdx.y * 128;
    const int bn = blockIdx.x * 128;
    const int tid = threadIdx.x;
    const int tx = tid & 15, ty = tid >> 4;
    const int lrow = tid >> 1, lcol = (tid & 1) * 4;
    const int brow = tid >> 5, bcol = (tid & 31) * 4;
    float c[8][8] = {};
    for (int k0 = 0; k0 < DIM; k0 += 8) {
        float4 av = *reinterpret_cast<const float4*>(x + (size_t)(bm + lrow) * DIM + k0 + lcol);
        float4 bv = *reinterpret_cast<const float4*>(A + (size_t)(k0 + brow) * DIM + bn + bcol);
        __syncthreads();
        As[lcol + 0][lrow] = av.x; As[lcol + 1][lrow] = av.y;
        As[lcol + 2][lrow] = av.z; As[lcol + 3][lrow] = av.w;
        *reinterpret_cast<float4*>(&Bs[brow][bcol]) = bv;
        __syncthreads();
#pragma unroll
        for (int kk = 0; kk < 8; ++kk) {
            float a[8], b[8];
            *reinterpret_cast<float4*>(a)     = *reinterpret_cast<const float4*>(&As[kk][ty * 8]);
            *reinterpret_cast<float4*>(a + 4) = *reinterpret_cast<const float4*>(&As[kk][ty * 8 + 4]);
            *reinterpret_cast<float4*>(b)     = *reinterpret_cast<const float4*>(&Bs[kk][tx * 8]);
            *reinterpret_cast<float4*>(b + 4) = *reinterpret_cast<const float4*>(&Bs[kk][tx * 8 + 4]);
#pragma unroll
            for (int m = 0; m < 8; ++m)
#pragma unroll
                for (int n = 0; n < 8; ++n) c[m][n] = fmaf(a[m], b[n], c[m][n]);
        }
    }
#pragma unroll
    for (int m = 0; m < 8; ++m) {
        float* dst = g_xw + (size_t)(bm + ty * 8 + m) * DIM + bn + tx * 8;
        *reinterpret_cast<float4*>(dst)     = make_float4(c[m][0], c[m][1], c[m][2], c[m][3]);
        *reinterpret_cast<float4*>(dst + 4) = make_float4(c[m][4], c[m][5], c[m][6], c[m][7]);
    }
}

// ---------------- fused Gram + top-10 ----------------
// CTA: 128 rows. Loop over 128-col tiles of all 16384 candidates.
// Gram tile -> shared Ds -> 2 scanner-threads per row maintain sorted top-10
// in registers; final pairwise merge -> g_idx.
__global__ __launch_bounds__(256, 1) void knn_kernel(const float* __restrict__ x) {
    __shared__ float As[8][132];
    __shared__ float Bs[8][132];
    __shared__ float sqs[128];
    extern __shared__ float Ds[];  // [128][136]

    const int bm = blockIdx.x * 128;
    const int tid = threadIdx.x;
    const int tx = tid & 15, ty = tid >> 4;
    const int lrow = tid >> 1, lcol = (tid & 1) * 4;
    const int srow = tid >> 1, shalf = tid & 1;
    const int rowglob = bm + srow;
    const float FINF = __int_as_float(0x7f800000);

    float bestd[KNN];
    int   besti[KNN];
#pragma unroll
    for (int t = 0; t < KNN; ++t) { bestd[t] = FINF; besti[t] = 0; }
    const float sqr = g_sq[rowglob];

    for (int jb = 0; jb < NROWS; jb += 128) {
        if (tid < 128) sqs[tid] = g_sq[jb + tid];  // prev scan finished (trailing sync)
        float c[8][8] = {};
        for (int k0 = 0; k0 < DIM; k0 += 8) {
            float4 av = *reinterpret_cast<const float4*>(x + (size_t)(bm + lrow) * DIM + k0 + lcol);
            float4 bv = *reinterpret_cast<const float4*>(x + (size_t)(jb + lrow) * DIM + k0 + lcol);
            __syncthreads();
            As[lcol + 0][lrow] = av.x; As[lcol + 1][lrow] = av.y;
            As[lcol + 2][lrow] = av.z; As[lcol + 3][lrow] = av.w;
            Bs[lcol + 0][lrow] = bv.x; Bs[lcol + 1][lrow] = bv.y;
            Bs[lcol + 2][lrow] = bv.z; Bs[lcol + 3][lrow] = bv.w;
            __syncthreads();
#pragma unroll
            for (int kk = 0; kk < 8; ++kk) {
                float a[8], b[8];
                *reinterpret_cast<float4*>(a)     = *reinterpret_cast<const float4*>(&As[kk][ty * 8]);
                *reinterpret_cast<float4*>(a + 4) = *reinterpret_cast<const float4*>(&As[kk][ty * 8 + 4]);
                *reinterpret_cast<float4*>(b)     = *reinterpret_cast<const float4*>(&Bs[kk][tx * 8]);
                *reinterpret_cast<float4*>(b + 4) = *reinterpret_cast<const float4*>(&Bs[kk][tx * 8 + 4]);
#pragma unroll
                for (int m = 0; m < 8; ++m)
#pragma unroll
                    for (int n = 0; n < 8; ++n) c[m][n] = fmaf(a[m], b[n], c[m][n]);
            }
        }
        // Gram tile -> shared
#pragma unroll
        for (int m = 0; m < 8; ++m) {
            float* dst = &Ds[(ty * 8 + m) * 136 + tx * 8];
            *reinterpret_cast<float4*>(dst)     = make_float4(c[m][0], c[m][1], c[m][2], c[m][3]);
            *reinterpret_cast<float4*>(dst + 4) = make_float4(c[m][4], c[m][5], c[m][6], c[m][7]);
        }
        __syncthreads();
        // scan my half-row (64 candidates), maintain sorted top-10
        const float* drow = &Ds[srow * 136 + shalf * 64];
        const int colbase = jb + shalf * 64;
#pragma unroll 4
        for (int s = 0; s < 64; s += 4) {
            float4 g4 = *reinterpret_cast<const float4*>(drow + s);
#pragma unroll
            for (int q = 0; q < 4; ++q) {
                const float g = (&g4.x)[q];
                const int col = colbase + s + q;
                if (col == rowglob) continue;  // exclude self
                float v = sqr + sqs[shalf * 64 + s + q];
                v = v - 2.0f * g;
                if (v < bestd[KNN - 1]) {      // strict < : stable, lower index wins ties
                    bestd[KNN - 1] = v; besti[KNN - 1] = col;
#pragma unroll
                    for (int t = KNN - 1; t > 0; --t) {
                        if (bestd[t] < bestd[t - 1]) {
                            float td = bestd[t]; bestd[t] = bestd[t - 1]; bestd[t - 1] = td;
                            int ti = besti[t]; besti[t] = besti[t - 1]; besti[t - 1] = ti;
                        }
                    }
                }
            }
        }
        __syncthreads();  // protect Ds/sqs reuse next tile
    }

    // merge the two half-row lists (even/odd thread pair) via shared
    float* md = Ds;                                  // 2560 floats
    int*   mi = reinterpret_cast<int*>(Ds + 2560);   // 2560 ints
#pragma unroll
    for (int t = 0; t < KNN; ++t) { md[tid * KNN + t] = bestd[t]; mi[tid * KNN + t] = besti[t]; }
    __syncthreads();
    if (shalf == 0) {
        const float* dA = &md[tid * KNN];
        const float* dB = &md[(tid + 1) * KNN];
        const int*   iA = &mi[tid * KNN];
        const int*   iB = &mi[(tid + 1) * KNN];
        int i = 0, j = 0;  // i+j = t < 10 always -> no OOB
        int* dst = g_idx + (size_t)rowglob * KNN;
        for (int t = 0; t < KNN; ++t) {
            float da = dA[i], db = dB[j];
            bool ta = (da < db) || (da == db && iA[i] < iB[j]);
            if (ta) dst[t] = iA[i++];
            else    dst[t] = iB[j++];
        }
    }
}

// ---------------- gather-sum: out[row] = sum over 10 neighbors of xW ----------------
__global__ void gather_kernel(float* __restrict__ out) {
    __shared__ int nb[KNN];
    const int row = blockIdx.x;
    if (threadIdx.x < KNN) nb[threadIdx.x] = g_idx[(size_t)row * KNN + threadIdx.x];
    __syncthreads();
    const int c = threadIdx.x * 4;
    float4 acc = make_float4(0.f, 0.f, 0.f, 0.f);
#pragma unroll
    for (int t = 0; t < KNN; ++t) {
        const float4 v = *reinterpret_cast<const float4*>(g_xw + (size_t)nb[t] * DIM + c);
        acc.x += v.x; acc.y += v.y; acc.z += v.z; acc.w += v.w;
    }
    *reinterpret_cast<float4*>(out + (size_t)row * DIM + c) = acc;
}

extern "C" void kernel_launch(void* const* d_in, const int* in_sizes, int n_in,
                              void* d_out, int out_size) {
    const float* x = (const float*)d_in[0];
    const float* A = (const float*)d_in[1];
    float* out = (float*)d_out;
    (void)in_sizes; (void)n_in; (void)out_size;

    // opt-in dynamic smem (69632 B) for knn_kernel; idempotent, deterministic
    cudaFuncSetAttribute(knn_kernel, cudaFuncAttributeMaxDynamicSharedMemorySize, 128 * 136 * 4);

    sq_kernel<<<NROWS / 8, 256>>>(x);                 // 2048 blocks x 8 warps = 16384 rows
    xw_kernel<<<dim3(4, 128), 256>>>(x, A);           // 16384x512 = 128x4 tiles
    knn_kernel<<<128, 256, 128 * 136 * 4>>>(x);       // 128 row-blocks
    gather_kernel<<<NROWS, 128>>>(out);
}

// round 6
// speedup vs baseline: 3.3260x; 3.3260x over previous
#include <cuda_runtime.h>
#include <cstdint>

#define NROWS 16384
#define DIM   512
#define KNN   10
#define NC2   12          // candidates kept per scanner thread
#define NCAND 24          // candidates per row

// ---- device scratch (allocation-free rule) ----
__device__ float  g_xw[NROWS * DIM];    // x @ A
__device__ float  g_sq[NROWS];          // fp32 row norms (for recall scan)
__device__ float2 g_sqd[NROWS];         // df64 row norms (for exact rescore)
__device__ int    g_cand[NROWS * NCAND];
__device__ int    g_idx[NROWS * KNN];

// ---- df64 helpers ----
__device__ __forceinline__ float2 df_add(float2 a, float2 b) {
    float s = a.x + b.x;
    float e = (fabsf(a.x) >= fabsf(b.x)) ? ((a.x - s) + b.x) : ((b.x - s) + a.x);
    e += a.y + b.y;
    float hi = s + e;
    return make_float2(hi, e - (hi - s));
}

#define MMA_TF32(c, a, b) \
    asm volatile("mma.sync.aligned.m16n8k8.row.col.f32.tf32.tf32.f32 " \
        "{%0,%1,%2,%3},{%4,%5,%6,%7},{%8,%9},{%0,%1,%2,%3};" \
        : "+f"((c)[0]), "+f"((c)[1]), "+f"((c)[2]), "+f"((c)[3]) \
        : "r"((a)[0]), "r"((a)[1]), "r"((a)[2]), "r"((a)[3]), \
          "r"((b)[0]), "r"((b)[1]))

// ================= row norms (fp32 + df64) =================
__global__ void sq_kernel(const float* __restrict__ x) {
    int row  = (blockIdx.x * blockDim.x + threadIdx.x) >> 5;
    int lane = threadIdx.x & 31;
    if (row >= NROWS) return;
    const float* xr = x + (size_t)row * DIM;
    float hi = 0.f, lo = 0.f;
#pragma unroll
    for (int k = 0; k < 16; ++k) {
        float a = xr[lane + 32 * k];
        float p = a * a;
        float e = fmaf(a, a, -p);
        float t = hi + p;
        float er = (fabsf(hi) >= fabsf(p)) ? ((hi - t) + p) : ((p - t) + hi);
        lo += er + e;
        hi = t;
    }
#pragma unroll
    for (int o = 16; o > 0; o >>= 1) {
        float oh = __shfl_xor_sync(0xffffffffu, hi, o);
        float ol = __shfl_xor_sync(0xffffffffu, lo, o);
        float s = hi + oh;
        float e = (fabsf(hi) >= fabsf(oh)) ? ((hi - s) + oh) : ((oh - s) + hi);
        e += lo + ol;
        hi = s + e;
        lo = e - (hi - s);
    }
    if (lane == 0) { g_sqd[row] = make_float2(hi, lo); g_sq[row] = hi + lo; }
}

// ================= xW = x @ A (fp32 FFMA) =================
__global__ __launch_bounds__(256, 1) void xw_kernel(const float* __restrict__ x,
                                                    const float* __restrict__ A) {
    __shared__ float As[8][132];
    __shared__ float Bs[8][132];
    const int bm = blockIdx.y * 128;
    const int bn = blockIdx.x * 128;
    const int tid = threadIdx.x;
    const int tx = tid & 15, ty = tid >> 4;
    const int lrow = tid >> 1, lcol = (tid & 1) * 4;
    const int brow = tid >> 5, bcol = (tid & 31) * 4;
    float c[8][8] = {};
    for (int k0 = 0; k0 < DIM; k0 += 8) {
        float4 av = *reinterpret_cast<const float4*>(x + (size_t)(bm + lrow) * DIM + k0 + lcol);
        float4 bv = *reinterpret_cast<const float4*>(A + (size_t)(k0 + brow) * DIM + bn + bcol);
        __syncthreads();
        As[lcol + 0][lrow] = av.x; As[lcol + 1][lrow] = av.y;
        As[lcol + 2][lrow] = av.z; As[lcol + 3][lrow] = av.w;
        *reinterpret_cast<float4*>(&Bs[brow][bcol]) = bv;
        __syncthreads();
#pragma unroll
        for (int kk = 0; kk < 8; ++kk) {
            float a[8], b[8];
            *reinterpret_cast<float4*>(a)     = *reinterpret_cast<const float4*>(&As[kk][ty * 8]);
            *reinterpret_cast<float4*>(a + 4) = *reinterpret_cast<const float4*>(&As[kk][ty * 8 + 4]);
            *reinterpret_cast<float4*>(b)     = *reinterpret_cast<const float4*>(&Bs[kk][tx * 8]);
            *reinterpret_cast<float4*>(b + 4) = *reinterpret_cast<const float4*>(&Bs[kk][tx * 8 + 4]);
#pragma unroll
            for (int m = 0; m < 8; ++m)
#pragma unroll
                for (int n = 0; n < 8; ++n) c[m][n] = fmaf(a[m], b[n], c[m][n]);
        }
    }
#pragma unroll
    for (int m = 0; m < 8; ++m) {
        float* dst = g_xw + (size_t)(bm + ty * 8 + m) * DIM + bn + tx * 8;
        *reinterpret_cast<float4*>(dst)     = make_float4(c[m][0], c[m][1], c[m][2], c[m][3]);
        *reinterpret_cast<float4*>(dst + 4) = make_float4(c[m][4], c[m][5], c[m][6], c[m][7]);
    }
}

// ================= Gram recall (pure tf32 mma.sync) + top-12 candidates =================
__global__ __launch_bounds__(256, 1) void knn_kernel(const float* __restrict__ x) {
    extern __shared__ float sm[];
    float* As  = sm;                 // [128][36]
    float* Bs  = As + 128 * 36;      // [256][36]
    float* sqs = Bs + 256 * 36;      // [256]
    float* Ds  = sqs + 256;          // [128][132]

    const int tid  = threadIdx.x;
    const int lane = tid & 31, wid = tid >> 5;
    const int wn = wid & 3, wm = wid >> 2;       // warp grid 2(M) x 4(N)
    const int g = lane >> 2, t = lane & 3;
    const int bm = blockIdx.x * 128;

    const int srow = tid >> 1, sh = tid & 1;     // 2 scanner threads / row
    const int rowg = bm + srow;

    const float FINF = __int_as_float(0x7f800000);
    float bestd[NC2];
    int   besti[NC2];
#pragma unroll
    for (int q = 0; q < NC2; ++q) { bestd[q] = FINF; besti[q] = 0; }

    for (int jt = 0; jt < 64; ++jt) {
        const int jb = jt * 256;
        __syncthreads();
        sqs[tid] = g_sq[jb + tid];

        float c[32][4];
#pragma unroll
        for (int i = 0; i < 32; ++i) { c[i][0] = 0.f; c[i][1] = 0.f; c[i][2] = 0.f; c[i][3] = 0.f; }

        for (int slab = 0; slab < 16; ++slab) {
            const int kb = slab * 32;
            __syncthreads();
#pragma unroll
            for (int i = tid; i < 1024; i += 256) {     // A: 128 x 32 (tf32-truncated ok via mma)
                int r = i >> 3, c4 = (i & 7) * 4;
                *reinterpret_cast<float4*>(As + r * 36 + c4) =
                    *reinterpret_cast<const float4*>(x + (size_t)(bm + r) * DIM + kb + c4);
            }
#pragma unroll
            for (int i = tid; i < 2048; i += 256) {     // B: 256 x 32
                int r = i >> 3, c4 = (i & 7) * 4;
                *reinterpret_cast<float4*>(Bs + r * 36 + c4) =
                    *reinterpret_cast<const float4*>(x + (size_t)(jb + r) * DIM + kb + c4);
            }
            __syncthreads();

            for (int kk = 0; kk < 4; ++kk) {
                const int k0 = kk * 8;
                uint32_t bh[8][2];
#pragma unroll
                for (int nt = 0; nt < 8; ++nt) {
                    const int brow = (wn * 64 + nt * 8 + g) * 36 + k0 + t;
                    // round to tf32 explicitly (mma truncates; rounding keeps error centered)
                    uint32_t b0, b1;
                    asm("cvt.rna.tf32.f32 %0, %1;" : "=r"(b0) : "f"(Bs[brow]));
                    asm("cvt.rna.tf32.f32 %0, %1;" : "=r"(b1) : "f"(Bs[brow + 4]));
                    bh[nt][0] = b0; bh[nt][1] = b1;
                }
#pragma unroll
                for (int mt = 0; mt < 4; ++mt) {
                    const int arow = (wm * 64 + mt * 16 + g) * 36 + k0 + t;
                    uint32_t ah[4];
                    asm("cvt.rna.tf32.f32 %0, %1;" : "=r"(ah[0]) : "f"(As[arow]));
                    asm("cvt.rna.tf32.f32 %0, %1;" : "=r"(ah[1]) : "f"(As[arow + 8 * 36]));
                    asm("cvt.rna.tf32.f32 %0, %1;" : "=r"(ah[2]) : "f"(As[arow + 4]));
                    asm("cvt.rna.tf32.f32 %0, %1;" : "=r"(ah[3]) : "f"(As[arow + 8 * 36 + 4]));
#pragma unroll
                    for (int nt = 0; nt < 8; ++nt)
                        MMA_TF32(c[mt * 8 + nt], ah, bh[nt]);
                }
            }
        }

        // epilogue: two 128-col halves through Ds
#pragma unroll
        for (int h = 0; h < 2; ++h) {
            if ((wn >> 1) == h) {
#pragma unroll
                for (int mt = 0; mt < 4; ++mt) {
#pragma unroll
                    for (int nt = 0; nt < 8; ++nt) {
                        const int r0 = wm * 64 + mt * 16 + g;
                        float* d0 = Ds + r0 * 132 + (wn & 1) * 64 + nt * 8 + 2 * t;
                        d0[0] = c[mt * 8 + nt][0];
                        d0[1] = c[mt * 8 + nt][1];
                        d0[8 * 132]     = c[mt * 8 + nt][2];
                        d0[8 * 132 + 1] = c[mt * 8 + nt][3];
                    }
                }
            }
            __syncthreads();
            const float* drow = Ds + srow * 132 + sh * 64;
            const int colbase = jb + h * 128 + sh * 64;
            const int sqb = h * 128 + sh * 64;
#pragma unroll 4
            for (int s = 0; s < 64; s += 4) {
                float4 g4 = *reinterpret_cast<const float4*>(drow + s);
#pragma unroll
                for (int q = 0; q < 4; ++q) {
                    float v = fmaf(-2.0f, (&g4.x)[q], sqs[sqb + s + q]);  // + const sqr: same order
                    const int col = colbase + s + q;
                    if (v < bestd[NC2 - 1] && col != rowg) {
                        bestd[NC2 - 1] = v; besti[NC2 - 1] = col;
#pragma unroll
                        for (int u = NC2 - 1; u > 0; --u) {
                            if (bestd[u] < bestd[u - 1]) {
                                float td = bestd[u]; bestd[u] = bestd[u - 1]; bestd[u - 1] = td;
                                int ti = besti[u]; besti[u] = besti[u - 1]; besti[u - 1] = ti;
                            }
                        }
                    }
                }
            }
            __syncthreads();
        }
    }

    // dump candidate sets (no merge: rescore treats them as an unordered set)
    int* dst = g_cand + (size_t)rowg * NCAND + sh * NC2;
#pragma unroll
    for (int q = 0; q < NC2; ++q) dst[q] = besti[q];
}

// ================= exact rescore: df64 d^2 on 24 candidates, rank top-10 =================
__global__ void rescore_kernel(const float* __restrict__ x) {
    const int warp = (blockIdx.x * blockDim.x + threadIdx.x) >> 5;
    const int lane = threadIdx.x & 31;
    if (warp >= NROWS) return;
    const int row = warp;
    const float2 sqr = g_sqd[row];
    const float* xr = x + (size_t)row * DIM;

    int myidx = 0;
    if (lane < NCAND) myidx = g_cand[(size_t)row * NCAND + lane];
    float myh = 0.f, myl = 0.f;

    for (int cc = 0; cc < NCAND; ++cc) {
        const int cidx = __shfl_sync(0xffffffffu, myidx, cc);
        const float* xc = x + (size_t)cidx * DIM;
        float hi = 0.f, lo = 0.f;
#pragma unroll
        for (int k = 0; k < 16; ++k) {
            float a = xr[lane + 32 * k];
            float b = xc[lane + 32 * k];
            float p = a * b;
            float e = fmaf(a, b, -p);
            float t2 = hi + p;
            float er = (fabsf(hi) >= fabsf(p)) ? ((hi - t2) + p) : ((p - t2) + hi);
            lo += er + e;
            hi = t2;
        }
#pragma unroll
        for (int o = 16; o > 0; o >>= 1) {
            float oh = __shfl_xor_sync(0xffffffffu, hi, o);
            float ol = __shfl_xor_sync(0xffffffffu, lo, o);
            float s = hi + oh;
            float e = (fabsf(hi) >= fabsf(oh)) ? ((hi - s) + oh) : ((oh - s) + hi);
            e += lo + ol;
            hi = s + e;
            lo = e - (hi - s);
        }
        const float2 sqc = g_sqd[cidx];
        float2 d2 = df_add(df_add(sqr, sqc), make_float2(-2.f * hi, -2.f * lo));
        if (lane == cc) { myh = d2.x; myl = d2.y; }
    }

    // rank among 24 candidates by (d2, idx); write top-10
    int rank = 0;
#pragma unroll
    for (int l = 0; l < NCAND; ++l) {
        float oh = __shfl_sync(0xffffffffu, myh, l);
        float ol = __shfl_sync(0xffffffffu, myl, l);
        int   oi = __shfl_sync(0xffffffffu, myidx, l);
        bool less = (oh < myh) || (oh == myh && (ol < myl || (ol == myl && oi < myidx)));
        rank += less;
    }
    if (lane < NCAND && rank < KNN)
        g_idx[(size_t)row * KNN + rank] = myidx;
}

// ================= gather-sum =================
__global__ void gather_kernel(float* __restrict__ out) {
    __shared__ int nb[KNN];
    const int row = blockIdx.x;
    if (threadIdx.x < KNN) nb[threadIdx.x] = g_idx[(size_t)row * KNN + threadIdx.x];
    __syncthreads();
    const int c = threadIdx.x * 4;
    float4 acc = make_float4(0.f, 0.f, 0.f, 0.f);
#pragma unroll
    for (int t = 0; t < KNN; ++t) {
        const float4 v = *reinterpret_cast<const float4*>(g_xw + (size_t)nb[t] * DIM + c);
        acc.x += v.x; acc.y += v.y; acc.z += v.z; acc.w += v.w;
    }
    *reinterpret_cast<float4*>(out + (size_t)row * DIM + c) = acc;
}

extern "C" void kernel_launch(void* const* d_in, const int* in_sizes, int n_in,
                              void* d_out, int out_size) {
    const float* x = (const float*)d_in[0];
    const float* A = (const float*)d_in[1];
    float* out = (float*)d_out;
    (void)in_sizes; (void)n_in; (void)out_size;

    // dynamic smem: (128*36 + 256*36 + 256 + 128*132) floats = 123904 B
    cudaFuncSetAttribute(knn_kernel, cudaFuncAttributeMaxDynamicSharedMemorySize, 123904);

    sq_kernel<<<NROWS / 8, 256>>>(x);
    xw_kernel<<<dim3(4, 128), 256>>>(x, A);
    knn_kernel<<<128, 256, 123904>>>(x);
    rescore_kernel<<<NROWS / 8, 256>>>(x);
    gather_kernel<<<NROWS, 128>>>(out);
}

// round 7
// speedup vs baseline: 3.5682x; 1.0728x over previous
#include <cuda_runtime.h>
#include <cstdint>

#define NROWS 16384
#define DIM   512
#define KNN   10
#define NC2   12          // candidates kept per scanner thread
#define NCAND 24          // candidates per row

// ---- device scratch (allocation-free rule) ----
__device__ float  g_xw[NROWS * DIM];    // x @ A
__device__ float  g_tf[NROWS * DIM];    // x pre-rounded to tf32 (rna)
__device__ float  g_sq[NROWS];          // fp32 row norms (for recall scan)
__device__ float2 g_sqd[NROWS];         // df64 row norms (for exact rescore)
__device__ int    g_cand[NROWS * NCAND];
__device__ int    g_idx[NROWS * KNN];

// ---- helpers ----
__device__ __forceinline__ float2 df_add(float2 a, float2 b) {
    float s = a.x + b.x;
    float e = (fabsf(a.x) >= fabsf(b.x)) ? ((a.x - s) + b.x) : ((b.x - s) + a.x);
    e += a.y + b.y;
    float hi = s + e;
    return make_float2(hi, e - (hi - s));
}
__device__ __forceinline__ uint32_t smem_u32(const void* p) {
    uint32_t a;
    asm("{ .reg .u64 t; cvta.to.shared.u64 t, %1; cvt.u32.u64 %0, t; }" : "=r"(a) : "l"(p));
    return a;
}
__device__ __forceinline__ void cpa16(uint32_t s, const void* g) {
    asm volatile("cp.async.cg.shared.global [%0], [%1], 16;" :: "r"(s), "l"(g));
}

#define MMA_TF32(c, a, b) \
    asm volatile("mma.sync.aligned.m16n8k8.row.col.f32.tf32.tf32.f32 " \
        "{%0,%1,%2,%3},{%4,%5,%6,%7},{%8,%9},{%0,%1,%2,%3};" \
        : "+f"((c)[0]), "+f"((c)[1]), "+f"((c)[2]), "+f"((c)[3]) \
        : "r"((a)[0]), "r"((a)[1]), "r"((a)[2]), "r"((a)[3]), \
          "r"((b)[0]), "r"((b)[1]))

// ================= prep: round x to tf32 =================
__global__ void tf_kernel(const float* __restrict__ x) {
    int i = blockIdx.x * blockDim.x + threadIdx.x;
    float4 v = reinterpret_cast<const float4*>(x)[i];
    float4 h;
#pragma unroll
    for (int c = 0; c < 4; ++c) {
        uint32_t hb; asm("cvt.rna.tf32.f32 %0, %1;" : "=r"(hb) : "f"((&v.x)[c]));
        (&h.x)[c] = __uint_as_float(hb);
    }
    reinterpret_cast<float4*>(g_tf)[i] = h;
}

// ================= row norms (fp32 + df64) =================
__global__ void sq_kernel(const float* __restrict__ x) {
    int row  = (blockIdx.x * blockDim.x + threadIdx.x) >> 5;
    int lane = threadIdx.x & 31;
    if (row >= NROWS) return;
    const float* xr = x + (size_t)row * DIM;
    float hi = 0.f, lo = 0.f;
#pragma unroll
    for (int k = 0; k < 16; ++k) {
        float a = xr[lane + 32 * k];
        float p = a * a;
        float e = fmaf(a, a, -p);
        float t = hi + p;
        float er = (fabsf(hi) >= fabsf(p)) ? ((hi - t) + p) : ((p - t) + hi);
        lo += er + e;
        hi = t;
    }
#pragma unroll
    for (int o = 16; o > 0; o >>= 1) {
        float oh = __shfl_xor_sync(0xffffffffu, hi, o);
        float ol = __shfl_xor_sync(0xffffffffu, lo, o);
        float s = hi + oh;
        float e = (fabsf(hi) >= fabsf(oh)) ? ((hi - s) + oh) : ((oh - s) + hi);
        e += lo + ol;
        hi = s + e;
        lo = e - (hi - s);
    }
    if (lane == 0) { g_sqd[row] = make_float2(hi, lo); g_sq[row] = hi + lo; }
}

// ================= xW = x @ A (fp32 FFMA) =================
__global__ __launch_bounds__(256, 1) void xw_kernel(const float* __restrict__ x,
                                                    const float* __restrict__ A) {
    __shared__ float As[8][132];
    __shared__ float Bs[8][132];
    const int bm = blockIdx.y * 128;
    const int bn = blockIdx.x * 128;
    const int tid = threadIdx.x;
    const int tx = tid & 15, ty = tid >> 4;
    const int lrow = tid >> 1, lcol = (tid & 1) * 4;
    const int brow = tid >> 5, bcol = (tid & 31) * 4;
    float c[8][8] = {};
    for (int k0 = 0; k0 < DIM; k0 += 8) {
        float4 av = *reinterpret_cast<const float4*>(x + (size_t)(bm + lrow) * DIM + k0 + lcol);
        float4 bv = *reinterpret_cast<const float4*>(A + (size_t)(k0 + brow) * DIM + bn + bcol);
        __syncthreads();
        As[lcol + 0][lrow] = av.x; As[lcol + 1][lrow] = av.y;
        As[lcol + 2][lrow] = av.z; As[lcol + 3][lrow] = av.w;
        *reinterpret_cast<float4*>(&Bs[brow][bcol]) = bv;
        __syncthreads();
#pragma unroll
        for (int kk = 0; kk < 8; ++kk) {
            float a[8], b[8];
            *reinterpret_cast<float4*>(a)     = *reinterpret_cast<const float4*>(&As[kk][ty * 8]);
            *reinterpret_cast<float4*>(a + 4) = *reinterpret_cast<const float4*>(&As[kk][ty * 8 + 4]);
            *reinterpret_cast<float4*>(b)     = *reinterpret_cast<const float4*>(&Bs[kk][tx * 8]);
            *reinterpret_cast<float4*>(b + 4) = *reinterpret_cast<const float4*>(&Bs[kk][tx * 8 + 4]);
#pragma unroll
            for (int m = 0; m < 8; ++m)
#pragma unroll
                for (int n = 0; n < 8; ++n) c[m][n] = fmaf(a[m], b[n], c[m][n]);
        }
    }
#pragma unroll
    for (int m = 0; m < 8; ++m) {
        float* dst = g_xw + (size_t)(bm + ty * 8 + m) * DIM + bn + tx * 8;
        *reinterpret_cast<float4*>(dst)     = make_float4(c[m][0], c[m][1], c[m][2], c[m][3]);
        *reinterpret_cast<float4*>(dst + 4) = make_float4(c[m][4], c[m][5], c[m][6], c[m][7]);
    }
}

// ================= Gram recall (tf32 mma.sync, cp.async double-buffered) =================
// SMEM (floats): A stages 2x[128][36] @0, B stages 2x[256][36] @9216,
//                sqs[256] @27648, Ds[128][132] @27904. Total 44800 fl = 179200 B.
__global__ __launch_bounds__(256, 1) void knn_kernel() {
    extern __shared__ float sm[];
    const uint32_t sbase = smem_u32(sm);
    float* sqs = sm + 27648;
    float* Ds  = sm + 27904;

    const int tid  = threadIdx.x;
    const int lane = tid & 31, wid = tid >> 5;
    const int wn = wid & 3, wm = wid >> 2;       // warp grid 2(M) x 4(N)
    const int g = lane >> 2, t = lane & 3;
    const int bm = blockIdx.x * 128;

    const int srow = tid >> 1, sh = tid & 1;     // 2 scanner threads / row
    const int rowg = bm + srow;

    const float FINF = __int_as_float(0x7f800000);
    float bestd[NC2];
    int   besti[NC2];
#pragma unroll
    for (int q = 0; q < NC2; ++q) { bestd[q] = FINF; besti[q] = 0; }

    for (int jt = 0; jt < 64; ++jt) {
        const int jb = jt * 256;
        __syncthreads();                 // prev j-tile scan done (sqs/Ds reuse)
        sqs[tid] = g_sq[jb + tid];

        float c[32][4];
#pragma unroll
        for (int i = 0; i < 32; ++i) { c[i][0] = 0.f; c[i][1] = 0.f; c[i][2] = 0.f; c[i][3] = 0.f; }

        // stage slab 0 into buffer 0
        {
            const uint32_t sA = sbase, sB = sbase + 36864;
#pragma unroll
            for (int i = tid; i < 1024; i += 256) {
                int r = i >> 3, cc = i & 7;
                cpa16(sA + r * 144 + cc * 16, g_tf + (size_t)(bm + r) * DIM + cc * 4);
            }
#pragma unroll
            for (int i = tid; i < 2048; i += 256) {
                int r = i >> 3, cc = i & 7;
                cpa16(sB + r * 144 + cc * 16, g_tf + (size_t)(jb + r) * DIM + cc * 4);
            }
            asm volatile("cp.async.commit_group;" ::: "memory");
        }

        for (int slab = 0; slab < 16; ++slab) {
            const int cur = slab & 1;
            if (slab < 15) {                     // stage next slab into other buffer
                const int nxt = (slab + 1) & 1;
                const int kb = (slab + 1) * 32;
                const uint32_t sA = sbase + nxt * 18432;
                const uint32_t sB = sbase + 36864 + nxt * 36864;
#pragma unroll
                for (int i = tid; i < 1024; i += 256) {
                    int r = i >> 3, cc = i & 7;
                    cpa16(sA + r * 144 + cc * 16, g_tf + (size_t)(bm + r) * DIM + kb + cc * 4);
                }
#pragma unroll
                for (int i = tid; i < 2048; i += 256) {
                    int r = i >> 3, cc = i & 7;
                    cpa16(sB + r * 144 + cc * 16, g_tf + (size_t)(jb + r) * DIM + kb + cc * 4);
                }
                asm volatile("cp.async.commit_group;" ::: "memory");
                asm volatile("cp.async.wait_group 1;" ::: "memory");
            } else {
                asm volatile("cp.async.wait_group 0;" ::: "memory");
            }
            __syncthreads();                    // current buffer ready for all warps

            const float* As = sm + cur * 4608;
            const float* Bs = sm + 9216 + cur * 9216;
#pragma unroll
            for (int kk = 0; kk < 4; ++kk) {
                const int k0 = kk * 8;
                uint32_t bh[8][2];
#pragma unroll
                for (int nt = 0; nt < 8; ++nt) {
                    const int brow = (wn * 64 + nt * 8 + g) * 36 + k0 + t;
                    bh[nt][0] = __float_as_uint(Bs[brow]);
                    bh[nt][1] = __float_as_uint(Bs[brow + 4]);
                }
#pragma unroll
                for (int mt = 0; mt < 4; ++mt) {
                    const int arow = (wm * 64 + mt * 16 + g) * 36 + k0 + t;
                    uint32_t ah[4];
                    ah[0] = __float_as_uint(As[arow]);
                    ah[1] = __float_as_uint(As[arow + 8 * 36]);
                    ah[2] = __float_as_uint(As[arow + 4]);
                    ah[3] = __float_as_uint(As[arow + 8 * 36 + 4]);
#pragma unroll
                    for (int nt = 0; nt < 8; ++nt)
                        MMA_TF32(c[mt * 8 + nt], ah, bh[nt]);
                }
            }
            __syncthreads();                    // all reads done before next overwrite
        }

        // epilogue: two 128-col halves through Ds
#pragma unroll
        for (int h = 0; h < 2; ++h) {
            if ((wn >> 1) == h) {
#pragma unroll
                for (int mt = 0; mt < 4; ++mt) {
#pragma unroll
                    for (int nt = 0; nt < 8; ++nt) {
                        const int r0 = wm * 64 + mt * 16 + g;
                        float* d0 = Ds + r0 * 132 + (wn & 1) * 64 + nt * 8 + 2 * t;
                        d0[0] = c[mt * 8 + nt][0];
                        d0[1] = c[mt * 8 + nt][1];
                        d0[8 * 132]     = c[mt * 8 + nt][2];
                        d0[8 * 132 + 1] = c[mt * 8 + nt][3];
                    }
                }
            }
            __syncthreads();
            const float* drow = Ds + srow * 132 + sh * 64;
            const int colbase = jb + h * 128 + sh * 64;
            const int sqb = h * 128 + sh * 64;
#pragma unroll 4
            for (int s = 0; s < 64; s += 4) {
                float4 g4 = *reinterpret_cast<const float4*>(drow + s);
#pragma unroll
                for (int q = 0; q < 4; ++q) {
                    float v = fmaf(-2.0f, (&g4.x)[q], sqs[sqb + s + q]);
                    const int col = colbase + s + q;
                    if (v < bestd[NC2 - 1] && col != rowg) {
                        bestd[NC2 - 1] = v; besti[NC2 - 1] = col;
#pragma unroll
                        for (int u = NC2 - 1; u > 0; --u) {
                            if (bestd[u] < bestd[u - 1]) {
                                float td = bestd[u]; bestd[u] = bestd[u - 1]; bestd[u - 1] = td;
                                int ti = besti[u]; besti[u] = besti[u - 1]; besti[u - 1] = ti;
                            }
                        }
                    }
                }
            }
            __syncthreads();
        }
    }

    // dump candidate sets (rescore treats them as an unordered set)
    int* dst = g_cand + (size_t)rowg * NCAND + sh * NC2;
#pragma unroll
    for (int q = 0; q < NC2; ++q) dst[q] = besti[q];
}

// ================= exact rescore: df64 d^2 on 24 candidates, rank top-10 =================
__global__ void rescore_kernel(const float* __restrict__ x) {
    const int warp = (blockIdx.x * blockDim.x + threadIdx.x) >> 5;
    const int lane = threadIdx.x & 31;
    if (warp >= NROWS) return;
    const int row = warp;
    const float2 sqr = g_sqd[row];
    const float* xr = x + (size_t)row * DIM;

    int myidx = 0;
    if (lane < NCAND) myidx = g_cand[(size_t)row * NCAND + lane];
    float myh = 0.f, myl = 0.f;

    for (int cc = 0; cc < NCAND; ++cc) {
        const int cidx = __shfl_sync(0xffffffffu, myidx, cc);
        const float* xc = x + (size_t)cidx * DIM;
        float hi = 0.f, lo = 0.f;
#pragma unroll
        for (int k = 0; k < 16; ++k) {
            float a = xr[lane + 32 * k];
            float b = xc[lane + 32 * k];
            float p = a * b;
            float e = fmaf(a, b, -p);
            float t2 = hi + p;
            float er = (fabsf(hi) >= fabsf(p)) ? ((hi - t2) + p) : ((p - t2) + hi);
            lo += er + e;
            hi = t2;
        }
#pragma unroll
        for (int o = 16; o > 0; o >>= 1) {
            float oh = __shfl_xor_sync(0xffffffffu, hi, o);
            float ol = __shfl_xor_sync(0xffffffffu, lo, o);
            float s = hi + oh;
            float e = (fabsf(hi) >= fabsf(oh)) ? ((hi - s) + oh) : ((oh - s) + hi);
            e += lo + ol;
            hi = s + e;
            lo = e - (hi - s);
        }
        const float2 sqc = g_sqd[cidx];
        float2 d2 = df_add(df_add(sqr, sqc), make_float2(-2.f * hi, -2.f * lo));
        if (lane == cc) { myh = d2.x; myl = d2.y; }
    }

    int rank = 0;
#pragma unroll
    for (int l = 0; l < NCAND; ++l) {
        float oh = __shfl_sync(0xffffffffu, myh, l);
        float ol = __shfl_sync(0xffffffffu, myl, l);
        int   oi = __shfl_sync(0xffffffffu, myidx, l);
        bool less = (oh < myh) || (oh == myh && (ol < myl || (ol == myl && oi < myidx)));
        rank += less;
    }
    if (lane < NCAND && rank < KNN)
        g_idx[(size_t)row * KNN + rank] = myidx;
}

// ================= gather-sum =================
__global__ void gather_kernel(float* __restrict__ out) {
    __shared__ int nb[KNN];
    const int row = blockIdx.x;
    if (threadIdx.x < KNN) nb[threadIdx.x] = g_idx[(size_t)row * KNN + threadIdx.x];
    __syncthreads();
    const int c = threadIdx.x * 4;
    float4 acc = make_float4(0.f, 0.f, 0.f, 0.f);
#pragma unroll
    for (int t = 0; t < KNN; ++t) {
        const float4 v = *reinterpret_cast<const float4*>(g_xw + (size_t)nb[t] * DIM + c);
        acc.x += v.x; acc.y += v.y; acc.z += v.z; acc.w += v.w;
    }
    *reinterpret_cast<float4*>(out + (size_t)row * DIM + c) = acc;
}

extern "C" void kernel_launch(void* const* d_in, const int* in_sizes, int n_in,
                              void* d_out, int out_size) {
    const float* x = (const float*)d_in[0];
    const float* A = (const float*)d_in[1];
    float* out = (float*)d_out;
    (void)in_sizes; (void)n_in; (void)out_size;

    cudaFuncSetAttribute(knn_kernel, cudaFuncAttributeMaxDynamicSharedMemorySize, 179200);

    tf_kernel<<<NROWS * DIM / 4 / 256, 256>>>(x);
    sq_kernel<<<NROWS / 8, 256>>>(x);
    xw_kernel<<<dim3(4, 128), 256>>>(x, A);
    knn_kernel<<<128, 256, 179200>>>();
    rescore_kernel<<<NROWS / 8, 256>>>(x);
    gather_kernel<<<NROWS, 128>>>(out);
}